// round 3
// baseline (speedup 1.0000x reference)
#include <cuda_runtime.h>
#include <math.h>

// Problem constants
#define L_    1024
#define B_    4
#define E_    1024
#define H_    16
#define DK_   64
#define TOPK_ 32
#define M_    (L_ * B_)   // 4096 rows for all GEMMs

// Scratch (no cudaMalloc allowed): Q,K,V in [B,H,L,DK], ctx in [L,B,E]
__device__ float g_q[B_ * H_ * L_ * DK_];
__device__ float g_k[B_ * H_ * L_ * DK_];
__device__ float g_v[B_ * H_ * L_ * DK_];
__device__ float g_ctx[L_ * B_ * E_];

// ---------------------------------------------------------------------------
// Tiled SGEMM core: C = A[M,K] @ W[N,K]^T + bias, M=4096, N=1024, K=1024
// Double-buffered smem (one __syncthreads per K-tile), register prefetch.
// ---------------------------------------------------------------------------
#define BM 128
#define BN 128
#define BK 16
#define NKT (E_ / BK)   // 64 K-tiles

struct GemmCoords {
    int tid, m0, n0, tm, tn, r0, r1, kk;
};

__device__ __forceinline__ void gemm_mainloop(
    const float* __restrict__ A, const float* __restrict__ W,
    float (&acc)[8][8], const GemmCoords& c,
    float (*As)[BK][BM], float (*Bs)[BK][BN])
{
    const float* Aload0 = A + (size_t)(c.m0 + c.r0) * E_ + c.kk;
    const float* Aload1 = A + (size_t)(c.m0 + c.r1) * E_ + c.kk;
    const float* Wload0 = W + (size_t)(c.n0 + c.r0) * E_ + c.kk;
    const float* Wload1 = W + (size_t)(c.n0 + c.r1) * E_ + c.kk;

    // Prologue: tile 0 -> smem[0]
    float4 av0 = *(const float4*)(Aload0);
    float4 av1 = *(const float4*)(Aload1);
    float4 bv0 = *(const float4*)(Wload0);
    float4 bv1 = *(const float4*)(Wload1);
    {
        float (*A0)[BM] = As[0]; float (*B0)[BN] = Bs[0];
        A0[c.kk + 0][c.r0] = av0.x; A0[c.kk + 1][c.r0] = av0.y;
        A0[c.kk + 2][c.r0] = av0.z; A0[c.kk + 3][c.r0] = av0.w;
        A0[c.kk + 0][c.r1] = av1.x; A0[c.kk + 1][c.r1] = av1.y;
        A0[c.kk + 2][c.r1] = av1.z; A0[c.kk + 3][c.r1] = av1.w;
        B0[c.kk + 0][c.r0] = bv0.x; B0[c.kk + 1][c.r0] = bv0.y;
        B0[c.kk + 2][c.r0] = bv0.z; B0[c.kk + 3][c.r0] = bv0.w;
        B0[c.kk + 0][c.r1] = bv1.x; B0[c.kk + 1][c.r1] = bv1.y;
        B0[c.kk + 2][c.r1] = bv1.z; B0[c.kk + 3][c.r1] = bv1.w;
    }
    __syncthreads();

    // Prefetch tile 1 into regs
    av0 = *(const float4*)(Aload0 + BK);
    av1 = *(const float4*)(Aload1 + BK);
    bv0 = *(const float4*)(Wload0 + BK);
    bv1 = *(const float4*)(Wload1 + BK);

    for (int kt = 0; kt < NKT; kt++) {
        const int cur = kt & 1;
        const int nxt = cur ^ 1;

        // Stage prefetched tile (kt+1) into the other buffer
        if (kt + 1 < NKT) {
            float (*An)[BM] = As[nxt]; float (*Bn)[BN] = Bs[nxt];
            An[c.kk + 0][c.r0] = av0.x; An[c.kk + 1][c.r0] = av0.y;
            An[c.kk + 2][c.r0] = av0.z; An[c.kk + 3][c.r0] = av0.w;
            An[c.kk + 0][c.r1] = av1.x; An[c.kk + 1][c.r1] = av1.y;
            An[c.kk + 2][c.r1] = av1.z; An[c.kk + 3][c.r1] = av1.w;
            Bn[c.kk + 0][c.r0] = bv0.x; Bn[c.kk + 1][c.r0] = bv0.y;
            Bn[c.kk + 2][c.r0] = bv0.z; Bn[c.kk + 3][c.r0] = bv0.w;
            Bn[c.kk + 0][c.r1] = bv1.x; Bn[c.kk + 1][c.r1] = bv1.y;
            Bn[c.kk + 2][c.r1] = bv1.z; Bn[c.kk + 3][c.r1] = bv1.w;
        }
        // Issue prefetch loads for tile kt+2 (overlap with compute below)
        if (kt + 2 < NKT) {
            const int ko = (kt + 2) * BK;
            av0 = *(const float4*)(Aload0 + ko);
            av1 = *(const float4*)(Aload1 + ko);
            bv0 = *(const float4*)(Wload0 + ko);
            bv1 = *(const float4*)(Wload1 + ko);
        }

        float (*Ac)[BM] = As[cur]; float (*Bc)[BN] = Bs[cur];
#pragma unroll
        for (int k = 0; k < BK; k++) {
            float a[8], b[8];
            *(float4*)(a)     = *(const float4*)&Ac[k][c.tm];
            *(float4*)(a + 4) = *(const float4*)&Ac[k][c.tm + 4];
            *(float4*)(b)     = *(const float4*)&Bc[k][c.tn];
            *(float4*)(b + 4) = *(const float4*)&Bc[k][c.tn + 4];
#pragma unroll
            for (int i = 0; i < 8; i++)
#pragma unroll
                for (int j = 0; j < 8; j++)
                    acc[i][j] = fmaf(a[i], b[j], acc[i][j]);
        }
        __syncthreads();
    }
}

__device__ __forceinline__ GemmCoords make_coords()
{
    GemmCoords c;
    c.tid = threadIdx.x;
    c.m0  = blockIdx.y * BM;
    c.n0  = blockIdx.x * BN;
    c.tm  = (c.tid >> 4) << 3;
    c.tn  = (c.tid & 15) << 3;
    c.r0  = c.tid >> 2;
    c.r1  = c.r0 + 64;
    c.kk  = (c.tid & 3) << 2;
    return c;
}

// Fused QKV: gridDim.z = 3 selects {query,key,value} x {wq,wk,wv}.
// Epilogue scatters [L*B, E] -> [B,H,L,DK] with q-scaling for z==0.
__global__ __launch_bounds__(256)
void qkv_gemm_kernel(const float* __restrict__ query,
                     const float* __restrict__ key,
                     const float* __restrict__ value,
                     const float* __restrict__ w_in,
                     const float* __restrict__ b_in)
{
    __shared__ float As[2][BK][BM];
    __shared__ float Bs[2][BK][BN];

    const int z = blockIdx.z;
    const float* A    = (z == 0) ? query : (z == 1) ? key : value;
    const float* W    = w_in + (size_t)z * E_ * E_;
    const float* bias = b_in + z * E_;
    float* C          = (z == 0) ? g_q : (z == 1) ? g_k : g_v;
    const float scale = (z == 0) ? 0.125f : 1.0f;  // DK^-0.5

    GemmCoords c = make_coords();
    float acc[8][8];
#pragma unroll
    for (int i = 0; i < 8; i++)
#pragma unroll
        for (int j = 0; j < 8; j++) acc[i][j] = 0.f;

    gemm_mainloop(A, W, acc, c, As, Bs);

    // m = l*B + b ; n = h*DK + d  ->  dst[((b*H + h)*L + l)*DK + d]
#pragma unroll
    for (int i = 0; i < 8; i++) {
        const int m = c.m0 + c.tm + i;
        const int l = m >> 2;       // /B_
        const int b = m & 3;        // %B_
        const int n_base = c.n0 + c.tn;  // multiple of 8 -> single head
        const int h = n_base >> 6;
        const int d = n_base & 63;
        float* dst = C + (size_t)(((b * H_ + h) * L_) + l) * DK_ + d;
#pragma unroll
        for (int j = 0; j < 8; j++)
            dst[j] = (acc[i][j] + bias[n_base + j]) * scale;
    }
}

// Output projection: plain [M, E] layout
__global__ __launch_bounds__(256)
void out_gemm_kernel(const float* __restrict__ out_w,
                     const float* __restrict__ out_b,
                     float* __restrict__ C)
{
    __shared__ float As[2][BK][BM];
    __shared__ float Bs[2][BK][BN];

    GemmCoords c = make_coords();
    float acc[8][8];
#pragma unroll
    for (int i = 0; i < 8; i++)
#pragma unroll
        for (int j = 0; j < 8; j++) acc[i][j] = 0.f;

    gemm_mainloop(g_ctx, out_w, acc, c, As, Bs);

#pragma unroll
    for (int i = 0; i < 8; i++) {
        const int m = c.m0 + c.tm + i;
        float* crow = C + (size_t)m * E_ + c.n0 + c.tn;
#pragma unroll
        for (int j = 0; j < 8; j++)
            crow[j] = acc[i][j] + out_b[c.n0 + c.tn + j];
    }
}

// ---------------------------------------------------------------------------
// Sparse top-k attention. Block = (l, b), warp h = head h, lane t = topk slot.
// Writes context [L,B,E] to g_ctx and attn.sum(axis=1)/H to attn_avg [B,L,TOPK].
// ---------------------------------------------------------------------------
__global__ __launch_bounds__(512)
void attn_kernel(const int* __restrict__ mask, float* __restrict__ attn_avg)
{
    const int l    = blockIdx.x;
    const int b    = blockIdx.y;
    const int h    = threadIdx.x >> 5;
    const int lane = threadIdx.x & 31;

    __shared__ float sq[H_][DK_];
    __shared__ float s_attn[H_][TOPK_];
    __shared__ int   s_idx[H_][TOPK_];

    // Stage q for this head in shared (broadcast reads later)
    const float* qrow = g_q + (size_t)(((b * H_ + h) * L_) + l) * DK_;
    sq[h][lane]      = qrow[lane];
    sq[h][lane + 32] = qrow[lane + 32];
    __syncwarp();

    // Scores: lane t owns top-k slot t
    const int idx = mask[(size_t)(((b * H_ + h) * L_) + l) * TOPK_ + lane];
    s_idx[h][lane] = idx;
    const float4* krow = (const float4*)(g_k + (size_t)(((b * H_ + h) * L_) + idx) * DK_);
    const float4* sq4  = (const float4*)sq[h];
    float s = 0.f;
#pragma unroll
    for (int j = 0; j < DK_ / 4; j++) {
        float4 kv = krow[j];
        float4 qv = sq4[j];
        s += kv.x * qv.x + kv.y * qv.y + kv.z * qv.z + kv.w * qv.w;
    }

    // Softmax across the 32 lanes (== TOPK)
    float mx = s;
#pragma unroll
    for (int off = 16; off > 0; off >>= 1)
        mx = fmaxf(mx, __shfl_xor_sync(0xFFFFFFFFu, mx, off));
    const float e = expf(s - mx);
    float sum = e;
#pragma unroll
    for (int off = 16; off > 0; off >>= 1)
        sum += __shfl_xor_sync(0xFFFFFFFFu, sum, off);
    const float a = e / sum;
    s_attn[h][lane] = a;
    __syncthreads();

    // Context: lane owns output dims (lane, lane+32); V rows read coalesced
    float acc0 = 0.f, acc1 = 0.f;
#pragma unroll
    for (int t = 0; t < TOPK_; t++) {
        const float at = s_attn[h][t];
        const float* vrow = g_v + (size_t)(((b * H_ + h) * L_) + s_idx[h][t]) * DK_;
        acc0 = fmaf(at, vrow[lane],      acc0);
        acc1 = fmaf(at, vrow[lane + 32], acc1);
    }
    float* crow = g_ctx + (size_t)(l * B_ + b) * E_ + h * DK_;
    crow[lane]      = acc0;
    crow[lane + 32] = acc1;

    // attn averaged over heads, deterministic fixed-order reduction
    if (threadIdx.x < TOPK_) {
        const int t = threadIdx.x;
        float ssum = 0.f;
#pragma unroll
        for (int hh = 0; hh < H_; hh++) ssum += s_attn[hh][t];
        attn_avg[(size_t)(b * L_ + l) * TOPK_ + t] = ssum * (1.f / H_);
    }
}

// ---------------------------------------------------------------------------
extern "C" void kernel_launch(void* const* d_in, const int* in_sizes, int n_in,
                              void* d_out, int out_size)
{
    const float* query = (const float*)d_in[0];
    const float* key   = (const float*)d_in[1];
    const float* value = (const float*)d_in[2];
    const int*   mask  = (const int*)  d_in[3];
    const float* w_in  = (const float*)d_in[4];
    const float* b_in  = (const float*)d_in[5];
    const float* out_w = (const float*)d_in[6];
    const float* out_b = (const float*)d_in[7];
    float* out = (float*)d_out;

    // Fused QKV projections (bias + q-scale + [L,B,E]->[B,H,L,DK] transpose)
    qkv_gemm_kernel<<<dim3(E_ / BN, M_ / BM, 3), 256>>>(query, key, value, w_in, b_in);

    // Sparse attention; second output segment written directly
    attn_kernel<<<dim3(L_, B_), 512>>>(mask, out + (size_t)L_ * B_ * E_);

    // Output projection into first output segment [L,B,E]
    out_gemm_kernel<<<dim3(E_ / BN, M_ / BM), 256>>>(out_w, out_b, out);
}

// round 5
// speedup vs baseline: 1.8784x; 1.8784x over previous
#include <cuda_runtime.h>
#include <math.h>
#include <stdint.h>

// Problem constants
#define L_    1024
#define B_    4
#define E_    1024
#define H_    16
#define DK_   64
#define TOPK_ 32
#define M_    (L_ * B_)   // 4096 rows for all GEMMs

// Scratch (no cudaMalloc allowed)
__device__ float g_q[B_ * H_ * L_ * DK_];
__device__ float g_k[B_ * H_ * L_ * DK_];
__device__ float g_v[B_ * H_ * L_ * DK_];
__device__ float g_ctx[L_ * B_ * E_];

// ---------------------------------------------------------------------------
// TF32 tensor-core GEMM: C = A[M,K] @ W[N,K]^T + bias
// Block tile 128x128, BK=16, 8 warps (4 x 2), warp tile 32x64.
// mma.sync.aligned.m16n8k8.row.col.f32.tf32.tf32.f32
// Padded smem strides make all fragment LDS.32 bank-conflict-free.
// ---------------------------------------------------------------------------
#define BM   128
#define BN   128
#define BKT  16
#define NKT  (E_ / BKT)   // 64
#define ASTR 20           // A smem row stride (floats): bank = 20g+tig injective
#define BSTR 136          // B smem row stride (floats): 136 % 32 = 8 -> 8*tig+g injective

__device__ __forceinline__ uint32_t f2tf32(float f) {
    uint32_t r;
    asm("cvt.rna.tf32.f32 %0, %1;" : "=r"(r) : "f"(f));
    return r;
}

__device__ __forceinline__ void mma_tf32(float (&d)[4],
                                         const uint32_t (&a)[4],
                                         uint32_t b0, uint32_t b1) {
    asm volatile(
        "mma.sync.aligned.m16n8k8.row.col.f32.tf32.tf32.f32 "
        "{%0,%1,%2,%3}, {%4,%5,%6,%7}, {%8,%9}, {%0,%1,%2,%3};"
        : "+f"(d[0]), "+f"(d[1]), "+f"(d[2]), "+f"(d[3])
        : "r"(a[0]), "r"(a[1]), "r"(a[2]), "r"(a[3]), "r"(b0), "r"(b1));
}

// Shared mainloop. acc[mt][nt][4] per-thread.
__device__ __forceinline__ void tf32_mainloop(
    const float* __restrict__ A, const float* __restrict__ W,
    int m0, int n0, float (&acc)[2][8][4],
    uint32_t (*As)[BM][ASTR], uint32_t (*Bs)[BKT][BSTR])
{
    const int tid  = threadIdx.x;
    const int lane = tid & 31;
    const int wid  = tid >> 5;
    const int wm   = wid & 3;    // 0..3 -> rows wm*32
    const int wn   = wid >> 2;   // 0..1 -> cols wn*64
    const int g    = lane >> 2;  // 0..7
    const int tig  = lane & 3;   // 0..3

    // Loader: thread handles row lm of both A-tile and W-tile, two k4-chunks
    const int lm  = tid >> 1;                 // 0..127
    const int ck0 = (tid & 1) * 2;            // chunk base 0 or 2
    const float* Ag = A + (size_t)(m0 + lm) * E_;
    const float* Wg = W + (size_t)(n0 + lm) * E_;

    float4 apf[2], bpf[2];

    auto prefetch = [&](int kt) {
#pragma unroll
        for (int it = 0; it < 2; it++) {
            const int kk = (ck0 + it) << 2;
            apf[it] = *(const float4*)(Ag + kt * BKT + kk);
            bpf[it] = *(const float4*)(Wg + kt * BKT + kk);
        }
    };
    auto stage = [&](int buf) {
#pragma unroll
        for (int it = 0; it < 2; it++) {
            const int kk = (ck0 + it) << 2;
            uint4 av;
            av.x = f2tf32(apf[it].x); av.y = f2tf32(apf[it].y);
            av.z = f2tf32(apf[it].z); av.w = f2tf32(apf[it].w);
            *(uint4*)&As[buf][lm][kk] = av;
            float bt[4];
            *(float4*)bt = bpf[it];
#pragma unroll
            for (int e = 0; e < 4; e++)
                Bs[buf][kk + e][lm] = f2tf32(bt[e]);
        }
    };

    // Prologue
    prefetch(0);
    stage(0);
    __syncthreads();
    prefetch(1);

    for (int kt = 0; kt < NKT; kt++) {
        const int cur = kt & 1;
        const int nxt = cur ^ 1;
        if (kt + 1 < NKT) stage(nxt);
        if (kt + 2 < NKT) prefetch(kt + 2);

#pragma unroll
        for (int ks = 0; ks < 2; ks++) {
            const int k0 = ks * 8;
            uint32_t a[2][4];
#pragma unroll
            for (int mt = 0; mt < 2; mt++) {
                const int mr = wm * 32 + mt * 16 + g;
                a[mt][0] = As[cur][mr][k0 + tig];
                a[mt][1] = As[cur][mr + 8][k0 + tig];
                a[mt][2] = As[cur][mr][k0 + tig + 4];
                a[mt][3] = As[cur][mr + 8][k0 + tig + 4];
            }
#pragma unroll
            for (int nt = 0; nt < 8; nt++) {
                const int nc = wn * 64 + nt * 8 + g;
                const uint32_t b0 = Bs[cur][k0 + tig][nc];
                const uint32_t b1 = Bs[cur][k0 + tig + 4][nc];
                mma_tf32(acc[0][nt], a[0], b0, b1);
                mma_tf32(acc[1][nt], a[1], b0, b1);
            }
        }
        __syncthreads();
    }
}

// Fused QKV GEMM: z selects {q,k,v}; epilogue scatters to [B,H,L,DK] + bias (+scale)
__global__ __launch_bounds__(256, 2)
void qkv_mma_kernel(const float* __restrict__ query,
                    const float* __restrict__ key,
                    const float* __restrict__ value,
                    const float* __restrict__ w_in,
                    const float* __restrict__ b_in)
{
    __shared__ uint32_t As[2][BM][ASTR];
    __shared__ uint32_t Bs[2][BKT][BSTR];

    const int z = blockIdx.z;
    const float* A    = (z == 0) ? query : (z == 1) ? key : value;
    const float* W    = w_in + (size_t)z * E_ * E_;
    const float* bias = b_in + z * E_;
    float* C          = (z == 0) ? g_q : (z == 1) ? g_k : g_v;
    const float scale = (z == 0) ? 0.125f : 1.0f;  // DK^-0.5

    const int m0 = blockIdx.y * BM;
    const int n0 = blockIdx.x * BN;

    float acc[2][8][4];
#pragma unroll
    for (int mt = 0; mt < 2; mt++)
#pragma unroll
        for (int nt = 0; nt < 8; nt++)
#pragma unroll
            for (int e = 0; e < 4; e++) acc[mt][nt][e] = 0.f;

    tf32_mainloop(A, W, m0, n0, acc, As, Bs);

    const int lane = threadIdx.x & 31;
    const int wid  = threadIdx.x >> 5;
    const int wm   = wid & 3;
    const int wn   = wid >> 2;
    const int g    = lane >> 2;
    const int tig  = lane & 3;

    // Warp covers exactly one head: h = (n0 + wn*64)/64
    const int h = (n0 >> 6) + wn;

#pragma unroll
    for (int mt = 0; mt < 2; mt++) {
        const int mr = m0 + wm * 32 + mt * 16 + g;   // rows mr and mr+8
        const int l0 = mr >> 2;                      // /B_
        const int bb = mr & 3;                       // %B_ (same for mr+8)
        const int l1 = l0 + 2;
        float* base = C + (size_t)(bb * H_ + h) * L_ * DK_;
#pragma unroll
        for (int nt = 0; nt < 8; nt++) {
            const int d  = nt * 8 + tig * 2;         // within-head col (even)
            const int nc = n0 + wn * 64 + d;
            const float bv0 = bias[nc];
            const float bv1 = bias[nc + 1];
            float2 r0 = make_float2((acc[mt][nt][0] + bv0) * scale,
                                    (acc[mt][nt][1] + bv1) * scale);
            float2 r1 = make_float2((acc[mt][nt][2] + bv0) * scale,
                                    (acc[mt][nt][3] + bv1) * scale);
            *(float2*)(base + (size_t)l0 * DK_ + d) = r0;
            *(float2*)(base + (size_t)l1 * DK_ + d) = r1;
        }
    }
}

// Output projection GEMM: plain [M, E] epilogue
__global__ __launch_bounds__(256, 2)
void out_mma_kernel(const float* __restrict__ out_w,
                    const float* __restrict__ out_b,
                    float* __restrict__ C)
{
    __shared__ uint32_t As[2][BM][ASTR];
    __shared__ uint32_t Bs[2][BKT][BSTR];

    const int m0 = blockIdx.y * BM;
    const int n0 = blockIdx.x * BN;

    float acc[2][8][4];
#pragma unroll
    for (int mt = 0; mt < 2; mt++)
#pragma unroll
        for (int nt = 0; nt < 8; nt++)
#pragma unroll
            for (int e = 0; e < 4; e++) acc[mt][nt][e] = 0.f;

    tf32_mainloop(g_ctx, out_w, m0, n0, acc, As, Bs);

    const int lane = threadIdx.x & 31;
    const int wid  = threadIdx.x >> 5;
    const int wm   = wid & 3;
    const int wn   = wid >> 2;
    const int g    = lane >> 2;
    const int tig  = lane & 3;

#pragma unroll
    for (int mt = 0; mt < 2; mt++) {
        const int mr = m0 + wm * 32 + mt * 16 + g;
#pragma unroll
        for (int nt = 0; nt < 8; nt++) {
            const int nc = n0 + wn * 64 + nt * 8 + tig * 2;
            const float bv0 = out_b[nc];
            const float bv1 = out_b[nc + 1];
            float2 r0 = make_float2(acc[mt][nt][0] + bv0, acc[mt][nt][1] + bv1);
            float2 r1 = make_float2(acc[mt][nt][2] + bv0, acc[mt][nt][3] + bv1);
            *(float2*)(C + (size_t)mr * E_ + nc)       = r0;
            *(float2*)(C + (size_t)(mr + 8) * E_ + nc) = r1;
        }
    }
}

// ---------------------------------------------------------------------------
// Sparse top-k attention. Block = (l, b), warp h = head h, lane t = topk slot.
// ---------------------------------------------------------------------------
__global__ __launch_bounds__(512)
void attn_kernel(const int* __restrict__ mask, float* __restrict__ attn_avg)
{
    const int l    = blockIdx.x;
    const int b    = blockIdx.y;
    const int h    = threadIdx.x >> 5;
    const int lane = threadIdx.x & 31;

    __shared__ float sq[H_][DK_];
    __shared__ float s_attn[H_][TOPK_];
    __shared__ int   s_idx[H_][TOPK_];

    const float* qrow = g_q + (size_t)(((b * H_ + h) * L_) + l) * DK_;
    sq[h][lane]      = qrow[lane];
    sq[h][lane + 32] = qrow[lane + 32];
    __syncwarp();

    const int idx = mask[(size_t)(((b * H_ + h) * L_) + l) * TOPK_ + lane];
    s_idx[h][lane] = idx;
    const float4* krow = (const float4*)(g_k + (size_t)(((b * H_ + h) * L_) + idx) * DK_);
    const float4* sq4  = (const float4*)sq[h];
    float s = 0.f;
#pragma unroll
    for (int j = 0; j < DK_ / 4; j++) {
        float4 kv = krow[j];
        float4 qv = sq4[j];
        s += kv.x * qv.x + kv.y * qv.y + kv.z * qv.z + kv.w * qv.w;
    }

    float mx = s;
#pragma unroll
    for (int off = 16; off > 0; off >>= 1)
        mx = fmaxf(mx, __shfl_xor_sync(0xFFFFFFFFu, mx, off));
    const float e = expf(s - mx);
    float sum = e;
#pragma unroll
    for (int off = 16; off > 0; off >>= 1)
        sum += __shfl_xor_sync(0xFFFFFFFFu, sum, off);
    const float a = e / sum;
    s_attn[h][lane] = a;
    __syncthreads();

    float acc0 = 0.f, acc1 = 0.f;
#pragma unroll
    for (int t = 0; t < TOPK_; t++) {
        const float at = s_attn[h][t];
        const float* vrow = g_v + (size_t)(((b * H_ + h) * L_) + s_idx[h][t]) * DK_;
        acc0 = fmaf(at, vrow[lane],      acc0);
        acc1 = fmaf(at, vrow[lane + 32], acc1);
    }
    float* crow = g_ctx + (size_t)(l * B_ + b) * E_ + h * DK_;
    crow[lane]      = acc0;
    crow[lane + 32] = acc1;

    if (threadIdx.x < TOPK_) {
        const int t = threadIdx.x;
        float ssum = 0.f;
#pragma unroll
        for (int hh = 0; hh < H_; hh++) ssum += s_attn[hh][t];
        attn_avg[(size_t)(b * L_ + l) * TOPK_ + t] = ssum * (1.f / H_);
    }
}

// ---------------------------------------------------------------------------
extern "C" void kernel_launch(void* const* d_in, const int* in_sizes, int n_in,
                              void* d_out, int out_size)
{
    const float* query = (const float*)d_in[0];
    const float* key   = (const float*)d_in[1];
    const float* value = (const float*)d_in[2];
    const int*   mask  = (const int*)  d_in[3];
    const float* w_in  = (const float*)d_in[4];
    const float* b_in  = (const float*)d_in[5];
    const float* out_w = (const float*)d_in[6];
    const float* out_b = (const float*)d_in[7];
    float* out = (float*)d_out;

    // Fused QKV projections on tensor cores (tf32)
    qkv_mma_kernel<<<dim3(E_ / BN, M_ / BM, 3), 256>>>(query, key, value, w_in, b_in);

    // Sparse attention; attn output segment written directly
    attn_kernel<<<dim3(L_, B_), 512>>>(mask, out + (size_t)L_ * B_ * E_);

    // Output projection on tensor cores (tf32)
    out_mma_kernel<<<dim3(E_ / BN, M_ / BM), 256>>>(out_w, out_b, out);
}